// round 1
// baseline (speedup 1.0000x reference)
#include <cuda_runtime.h>
#include <math.h>

#define BB 64
#define LL 256
#define HH 1024
#define EE 1024
#define VV 50257
#define H3 3072

// ---------------- scratch (__device__ globals; no allocation allowed) ----------
__device__ float g_x[BB * EE];                 // gathered embeddings
__device__ float g_gi_part[4 * BB * H3];       // split-K partials for gi
__device__ float g_gh_part[4 * BB * H3];       // split-K partials for gh
__device__ float g_cat[BB * 2 * HH];           // [h_new | context] rows of 2048
__device__ float g_hb[BB];                     // h_new . attn_b
__device__ float g_q[BB * HH];                 // h_new @ attn_w
__device__ float g_qpart[8 * BB * HH];
__device__ float g_scores[BB * LL];
__device__ float g_aw[BB * LL];
__device__ float g_cpart[8 * BB * HH];
__device__ float g_co[BB * HH];                // concat_out

// ---------------- embedding gather ------------------------------------------
__global__ void gather_emb(const int* __restrict__ seq,
                           const float* __restrict__ emb,
                           float* __restrict__ x) {
    int b = blockIdx.x;
    int t = threadIdx.x;
    const float4* src = (const float4*)(emb + (size_t)seq[b] * EE);
    float4* dst = (float4*)(x + (size_t)b * EE);
    dst[t] = src[t];
}

// ---------------- generic fp32 GEMM: C[64,N] = A[64,K] @ W[N,K]^T ------------
// BM=64, BN=128, BK=16, 128 threads, 8x8 micro-tile per thread.
// gridDim.y = split-K factor. If 1 -> direct write with bias; else partials.
__global__ __launch_bounds__(128)
void gemm_tn(const float* __restrict__ A, int lda,
             const float* __restrict__ W, int ldw,
             const float* __restrict__ bias,
             float* __restrict__ C, int ldc,
             float* __restrict__ Cpart,
             int N, int K) {
    __shared__ float As[16][64];
    __shared__ float Ws[16][128];
    const int tid = threadIdx.x;
    const int n0 = blockIdx.x * 128;
    const int kchunk = K / gridDim.y;
    const int k0 = blockIdx.y * kchunk;
    const int tx = tid & 15, ty = tid >> 4;
    const int am = tid >> 1, akq = (tid & 1) * 8;
    const int wn = tid;
    const bool wv = (n0 + wn) < N;
    const float* wrow = W + (size_t)(n0 + wn) * ldw;

    float acc[8][8];
#pragma unroll
    for (int i = 0; i < 8; i++)
#pragma unroll
        for (int j = 0; j < 8; j++) acc[i][j] = 0.f;

    for (int kt = k0; kt < k0 + kchunk; kt += 16) {
        float4 a0 = *(const float4*)(A + (size_t)am * lda + kt + akq);
        float4 a1 = *(const float4*)(A + (size_t)am * lda + kt + akq + 4);
        As[akq + 0][am] = a0.x; As[akq + 1][am] = a0.y;
        As[akq + 2][am] = a0.z; As[akq + 3][am] = a0.w;
        As[akq + 4][am] = a1.x; As[akq + 5][am] = a1.y;
        As[akq + 6][am] = a1.z; As[akq + 7][am] = a1.w;
        if (wv) {
#pragma unroll
            for (int kk = 0; kk < 16; kk += 4) {
                float4 w = *(const float4*)(wrow + kt + kk);
                Ws[kk + 0][wn] = w.x; Ws[kk + 1][wn] = w.y;
                Ws[kk + 2][wn] = w.z; Ws[kk + 3][wn] = w.w;
            }
        } else {
#pragma unroll
            for (int kk = 0; kk < 16; kk++) Ws[kk][wn] = 0.f;
        }
        __syncthreads();
#pragma unroll
        for (int k = 0; k < 16; k++) {
            float4 av0 = *(const float4*)&As[k][ty * 8];
            float4 av1 = *(const float4*)&As[k][ty * 8 + 4];
            float4 bv0 = *(const float4*)&Ws[k][tx * 8];
            float4 bv1 = *(const float4*)&Ws[k][tx * 8 + 4];
            float ar[8] = {av0.x, av0.y, av0.z, av0.w, av1.x, av1.y, av1.z, av1.w};
            float br[8] = {bv0.x, bv0.y, bv0.z, bv0.w, bv1.x, bv1.y, bv1.z, bv1.w};
#pragma unroll
            for (int i = 0; i < 8; i++)
#pragma unroll
                for (int j = 0; j < 8; j++)
                    acc[i][j] = fmaf(ar[i], br[j], acc[i][j]);
        }
        __syncthreads();
    }

    if (gridDim.y == 1) {
#pragma unroll
        for (int i = 0; i < 8; i++) {
            int m = ty * 8 + i;
#pragma unroll
            for (int j = 0; j < 8; j++) {
                int c = n0 + tx * 8 + j;
                if (c < N)
                    C[(size_t)m * ldc + c] = acc[i][j] + (bias ? bias[c] : 0.f);
            }
        }
    } else {
        float* P = Cpart + (size_t)blockIdx.y * 64 * (size_t)N;
#pragma unroll
        for (int i = 0; i < 8; i++) {
            int m = ty * 8 + i;
#pragma unroll
            for (int j = 0; j < 8; j++) {
                int c = n0 + tx * 8 + j;
                if (c < N) P[(size_t)m * N + c] = acc[i][j];
            }
        }
    }
}

// ---------------- GEMM, W not transposed: C[64,N] = A[64,K] @ W[K,N] ---------
__global__ __launch_bounds__(128)
void gemm_nn(const float* __restrict__ A, int lda,
             const float* __restrict__ W, int ldw,
             float* __restrict__ Cpart,
             int N, int K) {
    __shared__ float As[16][64];
    __shared__ float Ws[16][128];
    const int tid = threadIdx.x;
    const int n0 = blockIdx.x * 128;
    const int kchunk = K / gridDim.y;
    const int k0 = blockIdx.y * kchunk;
    const int tx = tid & 15, ty = tid >> 4;
    const int am = tid >> 1, akq = (tid & 1) * 8;
    const int wk = tid >> 3, wnq = (tid & 7) * 16;

    float acc[8][8];
#pragma unroll
    for (int i = 0; i < 8; i++)
#pragma unroll
        for (int j = 0; j < 8; j++) acc[i][j] = 0.f;

    for (int kt = k0; kt < k0 + kchunk; kt += 16) {
        float4 a0 = *(const float4*)(A + (size_t)am * lda + kt + akq);
        float4 a1 = *(const float4*)(A + (size_t)am * lda + kt + akq + 4);
        As[akq + 0][am] = a0.x; As[akq + 1][am] = a0.y;
        As[akq + 2][am] = a0.z; As[akq + 3][am] = a0.w;
        As[akq + 4][am] = a1.x; As[akq + 5][am] = a1.y;
        As[akq + 6][am] = a1.z; As[akq + 7][am] = a1.w;
#pragma unroll
        for (int q = 0; q < 4; q++) {
            int n = n0 + wnq + q * 4;
            float4 w;
            if (n + 3 < N) w = *(const float4*)(W + (size_t)(kt + wk) * ldw + n);
            else w = make_float4(0.f, 0.f, 0.f, 0.f);
            Ws[wk][wnq + q * 4 + 0] = w.x; Ws[wk][wnq + q * 4 + 1] = w.y;
            Ws[wk][wnq + q * 4 + 2] = w.z; Ws[wk][wnq + q * 4 + 3] = w.w;
        }
        __syncthreads();
#pragma unroll
        for (int k = 0; k < 16; k++) {
            float4 av0 = *(const float4*)&As[k][ty * 8];
            float4 av1 = *(const float4*)&As[k][ty * 8 + 4];
            float4 bv0 = *(const float4*)&Ws[k][tx * 8];
            float4 bv1 = *(const float4*)&Ws[k][tx * 8 + 4];
            float ar[8] = {av0.x, av0.y, av0.z, av0.w, av1.x, av1.y, av1.z, av1.w};
            float br[8] = {bv0.x, bv0.y, bv0.z, bv0.w, bv1.x, bv1.y, bv1.z, bv1.w};
#pragma unroll
            for (int i = 0; i < 8; i++)
#pragma unroll
                for (int j = 0; j < 8; j++)
                    acc[i][j] = fmaf(ar[i], br[j], acc[i][j]);
        }
        __syncthreads();
    }
    float* P = Cpart + (size_t)blockIdx.y * 64 * (size_t)N;
#pragma unroll
    for (int i = 0; i < 8; i++) {
        int m = ty * 8 + i;
#pragma unroll
        for (int j = 0; j < 8; j++) {
            int c = n0 + tx * 8 + j;
            if (c < N) P[(size_t)m * N + c] = acc[i][j];
        }
    }
}

// ---------------- split-K reduce + bias + optional tanh ----------------------
__global__ void reduce_ba(const float* __restrict__ P, int nsplit, int ntot,
                          int N, const float* __restrict__ bias,
                          float* __restrict__ C, int act) {
    int idx = blockIdx.x * blockDim.x + threadIdx.x;
    if (idx >= ntot) return;
    float s = 0.f;
    for (int p = 0; p < nsplit; p++) s += P[(size_t)p * ntot + idx];
    if (bias) s += bias[idx % N];
    if (act) s = tanhf(s);
    C[idx] = s;
}

// ---------------- GRU gate combine ------------------------------------------
__global__ void gru_combine(const float* __restrict__ gi_p,
                            const float* __restrict__ gh_p,
                            const float* __restrict__ b_ih,
                            const float* __restrict__ b_hh,
                            const float* __restrict__ hprev,
                            float* __restrict__ cat,
                            float* __restrict__ out_hidden) {
    int idx = blockIdx.x * blockDim.x + threadIdx.x;  // 65536
    int b = idx >> 10, j = idx & 1023;
    float ir = 0.f, iz = 0.f, in_ = 0.f, hr = 0.f, hz = 0.f, hn = 0.f;
#pragma unroll
    for (int s = 0; s < 4; s++) {
        size_t base = (size_t)s * BB * H3 + (size_t)b * H3 + j;
        ir += gi_p[base];           hr += gh_p[base];
        iz += gi_p[base + HH];      hz += gh_p[base + HH];
        in_ += gi_p[base + 2 * HH]; hn += gh_p[base + 2 * HH];
    }
    ir += b_ih[j]; iz += b_ih[HH + j]; in_ += b_ih[2 * HH + j];
    hr += b_hh[j]; hz += b_hh[HH + j]; hn += b_hh[2 * HH + j];
    float r = 1.f / (1.f + expf(-(ir + hr)));
    float z = 1.f / (1.f + expf(-(iz + hz)));
    float n = tanhf(in_ + r * hn);
    float hp = hprev[(size_t)b * HH + j];
    float hnew = (1.f - z) * n + z * hp;
    cat[(size_t)b * 2048 + j] = hnew;
    out_hidden[idx] = hnew;
}

// ---------------- hb[b] = h_new[b] . attn_b ----------------------------------
__global__ void hb_kernel(const float* __restrict__ cat,
                          const float* __restrict__ attn_b,
                          float* __restrict__ hb) {
    int b = blockIdx.x, t = threadIdx.x;
    __shared__ float sm[256];
    float s = 0.f;
#pragma unroll
    for (int i = 0; i < 4; i++) {
        int j = t + 256 * i;
        s += cat[(size_t)b * 2048 + j] * attn_b[j];
    }
    sm[t] = s;
    __syncthreads();
    for (int st = 128; st > 0; st >>= 1) {
        if (t < st) sm[t] += sm[t + st];
        __syncthreads();
    }
    if (t == 0) hb[b] = sm[0];
}

// ---------------- scores[b,l] = q[b] . enc[l,b] + hb[b] ----------------------
__global__ void scores_kernel(const float* __restrict__ q,
                              const float* __restrict__ enc,
                              const float* __restrict__ hb,
                              float* __restrict__ scores) {
    int pair = blockIdx.x * 8 + (threadIdx.x >> 5);
    int lane = threadIdx.x & 31;
    int b = pair >> 8, l = pair & 255;
    const float* e = enc + ((size_t)l * BB + b) * HH;
    const float* qr = q + (size_t)b * HH;
    float s = 0.f;
#pragma unroll
    for (int i = 0; i < 8; i++) {
        int h = lane * 4 + i * 128;
        float4 ev = *(const float4*)(e + h);
        float4 qv = *(const float4*)(qr + h);
        s += ev.x * qv.x + ev.y * qv.y + ev.z * qv.z + ev.w * qv.w;
    }
#pragma unroll
    for (int o = 16; o > 0; o >>= 1) s += __shfl_xor_sync(0xffffffffu, s, o);
    if (lane == 0) scores[(size_t)b * LL + l] = s + hb[b];
}

// ---------------- softmax over L=256 per batch --------------------------------
__global__ void softmax_kernel(const float* __restrict__ scores,
                               float* __restrict__ aw,
                               float* __restrict__ out_attn) {
    int b = blockIdx.x, t = threadIdx.x;
    __shared__ float sm[256];
    float v = scores[(size_t)b * LL + t];
    sm[t] = v;
    __syncthreads();
    for (int s = 128; s > 0; s >>= 1) {
        if (t < s) sm[t] = fmaxf(sm[t], sm[t + s]);
        __syncthreads();
    }
    float mx = sm[0];
    __syncthreads();
    float e = expf(v - mx);
    sm[t] = e;
    __syncthreads();
    for (int s = 128; s > 0; s >>= 1) {
        if (t < s) sm[t] += sm[t + s];
        __syncthreads();
    }
    float w = e / sm[0];
    aw[(size_t)b * LL + t] = w;
    out_attn[(size_t)b * LL + t] = w;
}

// ---------------- context[b,h] = sum_l aw[b,l] * enc[l,b,h] ------------------
__global__ void context_kernel(const float* __restrict__ aw,
                               const float* __restrict__ enc,
                               float* __restrict__ cat) {
    int b = blockIdx.x, t = threadIdx.x;
    __shared__ float aws[256];
    aws[t] = aw[(size_t)b * LL + t];
    __syncthreads();
    float a0 = 0.f, a1 = 0.f, a2 = 0.f, a3 = 0.f;
    for (int l = 0; l < LL; l += 2) {
        float w0 = aws[l], w1 = aws[l + 1];
        const float* e0 = enc + ((size_t)l * BB + b) * HH + t;
        const float* e1 = e0 + (size_t)BB * HH;
        a0 += w0 * e0[0]   + w1 * e1[0];
        a1 += w0 * e0[256] + w1 * e1[256];
        a2 += w0 * e0[512] + w1 * e1[512];
        a3 += w0 * e0[768] + w1 * e1[768];
    }
    float* dst = cat + (size_t)b * 2048 + 1024;
    dst[t] = a0; dst[t + 256] = a1; dst[t + 512] = a2; dst[t + 768] = a3;
}

// ---------------- launch ------------------------------------------------------
extern "C" void kernel_launch(void* const* d_in, const int* in_sizes, int n_in,
                              void* d_out, int out_size) {
    const int*   seq  = (const int*)d_in[0];
    const float* h0   = (const float*)d_in[1];
    const float* enc  = (const float*)d_in[2];
    const float* emb  = (const float*)d_in[3];
    const float* w_ih = (const float*)d_in[4];
    const float* w_hh = (const float*)d_in[5];
    const float* b_ih = (const float*)d_in[6];
    const float* b_hh = (const float*)d_in[7];
    const float* attw = (const float*)d_in[8];
    const float* attb = (const float*)d_in[9];
    const float* cw   = (const float*)d_in[10];
    const float* cb   = (const float*)d_in[11];
    const float* ow   = (const float*)d_in[12];
    const float* ob   = (const float*)d_in[13];

    float* out        = (float*)d_out;                  // [B, V]
    float* out_hidden = out + (size_t)BB * VV;          // [B, H]
    float* out_attn   = out_hidden + (size_t)BB * HH;   // [B, L]

    float *px, *pgi, *pgh, *pcat, *phb, *pq, *pqp, *psc, *paw, *pcp, *pco;
    cudaGetSymbolAddress((void**)&px,  g_x);
    cudaGetSymbolAddress((void**)&pgi, g_gi_part);
    cudaGetSymbolAddress((void**)&pgh, g_gh_part);
    cudaGetSymbolAddress((void**)&pcat, g_cat);
    cudaGetSymbolAddress((void**)&phb, g_hb);
    cudaGetSymbolAddress((void**)&pq,  g_q);
    cudaGetSymbolAddress((void**)&pqp, g_qpart);
    cudaGetSymbolAddress((void**)&psc, g_scores);
    cudaGetSymbolAddress((void**)&paw, g_aw);
    cudaGetSymbolAddress((void**)&pcp, g_cpart);
    cudaGetSymbolAddress((void**)&pco, g_co);

    // 1) embedding gather
    gather_emb<<<BB, 256>>>(seq, emb, px);

    // 2-3) GRU gate GEMMs (split-K=4): gi = x@w_ih^T, gh = h@w_hh^T
    gemm_tn<<<dim3(24, 4), 128>>>(px, EE, w_ih, EE, nullptr, nullptr, 0, pgi, H3, EE);
    gemm_tn<<<dim3(24, 4), 128>>>(h0, HH, w_hh, HH, nullptr, nullptr, 0, pgh, H3, HH);

    // 4) combine gates -> h_new (also writes hidden output)
    gru_combine<<<256, 256>>>(pgi, pgh, b_ih, b_hh, h0, pcat, out_hidden);

    // 5) hb = h_new . attn_b
    hb_kernel<<<BB, 256>>>(pcat, attb, phb);

    // 6-7) q = h_new @ attn_w  (split-K=8, then reduce)
    gemm_nn<<<dim3(8, 8), 128>>>(pcat, 2048, attw, HH, pqp, HH, HH);
    reduce_ba<<<(BB * HH) / 256, 256>>>(pqp, 8, BB * HH, HH, nullptr, pq, 0);

    // 8) scores = q . enc + hb
    scores_kernel<<<2048, 256>>>(pq, enc, phb, psc);

    // 9) softmax -> attn_weights
    softmax_kernel<<<BB, 256>>>(psc, paw, out_attn);

    // 10) context = aw @ enc
    context_kernel<<<BB, 256>>>(paw, enc, pcat);

    // 11-12) concat_out = tanh([h_new|context] @ concat_w^T + concat_b)
    gemm_tn<<<dim3(8, 8), 128>>>(pcat, 2048, cw, 2048, nullptr, nullptr, 0, pcp, HH, 2048);
    reduce_ba<<<(BB * HH) / 256, 256>>>(pcp, 8, BB * HH, HH, cb, pco, 1);

    // 13) output = concat_out @ out_w^T + out_b   (the big one: N=50257)
    gemm_tn<<<dim3((VV + 127) / 128, 1), 128>>>(pco, HH, ow, HH, ob, out, VV,
                                                nullptr, VV, HH);
}

// round 3
// speedup vs baseline: 1.4528x; 1.4528x over previous
#include <cuda_runtime.h>
#include <cuda_bf16.h>
#include <math.h>
#include <stdint.h>

#define BB 64
#define LL 256
#define HH 1024
#define EE 1024
#define VV 50257
#define H3 3072

// ================= scratch (__device__ globals) =============================
__device__ __align__(16) __nv_bfloat16 g_xhi[BB * 1024];
__device__ __align__(16) __nv_bfloat16 g_xlo[BB * 1024];
__device__ __align__(16) __nv_bfloat16 g_hhi[BB * 1024];
__device__ __align__(16) __nv_bfloat16 g_hlo[BB * 1024];
__device__ __align__(16) __nv_bfloat16 g_chi[BB * 1024];
__device__ __align__(16) __nv_bfloat16 g_clo[BB * 1024];
__device__ float g_gi[BB * H3];
__device__ float g_gh[BB * H3];
__device__ float g_cat[BB * 2 * HH];
__device__ float g_hb[BB];
__device__ float g_q[BB * HH];
__device__ float g_qpart[16 * BB * HH];
__device__ float g_scores[BB * LL];
__device__ float g_aw[BB * LL];
__device__ float g_cpart[16 * BB * HH];
__device__ float g_co[BB * HH];

// ================= helpers ===================================================
__device__ __forceinline__ uint32_t smem_u32(const void* p) {
    uint32_t a;
    asm("{ .reg .u64 t; cvta.to.shared.u64 t, %1; cvt.u32.u64 %0, t; }"
        : "=r"(a) : "l"(p));
    return a;
}

__device__ __forceinline__ void ldsm_x4(uint32_t addr, uint32_t& d0, uint32_t& d1,
                                        uint32_t& d2, uint32_t& d3) {
    asm volatile("ldmatrix.sync.aligned.m8n8.x4.shared.b16 {%0,%1,%2,%3}, [%4];"
                 : "=r"(d0), "=r"(d1), "=r"(d2), "=r"(d3) : "r"(addr));
}

__device__ __forceinline__ void mma_bf16(float* c, uint32_t a0, uint32_t a1,
                                         uint32_t a2, uint32_t a3,
                                         uint32_t b0, uint32_t b1) {
    asm volatile(
        "mma.sync.aligned.m16n8k16.row.col.f32.bf16.bf16.f32 "
        "{%0,%1,%2,%3}, {%4,%5,%6,%7}, {%8,%9}, {%0,%1,%2,%3};"
        : "+f"(c[0]), "+f"(c[1]), "+f"(c[2]), "+f"(c[3])
        : "r"(a0), "r"(a1), "r"(a2), "r"(a3), "r"(b0), "r"(b1));
}

__device__ __forceinline__ uint32_t pack_bf(float a, float b) {
    __nv_bfloat162 t = __floats2bfloat162_rn(a, b);
    return *reinterpret_cast<uint32_t*>(&t);
}

// ================= fused-convert HMMA GEMM ===================================
// C[64, n] = sum_k fp32(A[64,k]) * W[n,k]  (+bias), bf16 hi/lo 3-pass.
// A given as precomputed hi/lo bf16 [64, K]. W fp32 [Ntot, K] row-major,
// converted to bf16 hi/lo in-register while streaming (read exactly once).
// Block tile 64x128, 256 threads (8 warps of 16x64). K chunk = 32.
#define STR 40  // smem row stride in bf16 elements (80B, conflict-free ldmatrix)

__global__ __launch_bounds__(256, 2)
void hmma_gemm(const __nv_bfloat16* __restrict__ Ahi0, const __nv_bfloat16* __restrict__ Alo0,
               const float* __restrict__ W0, float* __restrict__ C0,
               const __nv_bfloat16* __restrict__ Ahi1, const __nv_bfloat16* __restrict__ Alo1,
               const float* __restrict__ W1, float* __restrict__ C1,
               const float* __restrict__ bias, int Ntot, int K, int ldc) {
    __shared__ __nv_bfloat16 sAhi[64 * STR];
    __shared__ __nv_bfloat16 sAlo[64 * STR];
    __shared__ __nv_bfloat16 sWhi[128 * STR];
    __shared__ __nv_bfloat16 sWlo[128 * STR];

    const __nv_bfloat16* Ahi = blockIdx.y ? Ahi1 : Ahi0;
    const __nv_bfloat16* Alo = blockIdx.y ? Alo1 : Alo0;
    const float* W = blockIdx.y ? W1 : W0;
    float* C = blockIdx.y ? C1 : C0;

    const int tid = threadIdx.x, wid = tid >> 5, lane = tid & 31;
    const int wr = wid & 3, wc = wid >> 2;       // warp row/col group
    const int n0 = blockIdx.x * 128;

    // staging ids
    const int r = tid >> 1, hf = tid & 1;        // W: row 0..127, k-half
    const bool wv = (n0 + r) < Ntot;
    const float* wrow = W + (size_t)(n0 + r) * K + hf * 16;
    const __nv_bfloat16* arow_hi = Ahi + (size_t)(r & 63) * K + hf * 16;
    const __nv_bfloat16* arow_lo = Alo + (size_t)(r & 63) * K + hf * 16;
    const bool do_a = (tid < 128);

    // precomputed ldmatrix addresses (smem layout fixed across chunks)
    const int am = lane >> 3, aln = lane & 7;
    const int arow2 = wr * 16 + aln + (am & 1) * 8;
    const int akoff = (am >> 1) * 8;
    uint32_t aAddrHi[2], aAddrLo[2];
#pragma unroll
    for (int ks = 0; ks < 2; ks++) {
        aAddrHi[ks] = smem_u32(&sAhi[arow2 * STR + ks * 16 + akoff]);
        aAddrLo[ks] = smem_u32(&sAlo[arow2 * STR + ks * 16 + akoff]);
    }
    const int brow_base = wc * 64 + aln + (am >> 1) * 8;
    const int bkoff = (am & 1) * 8;
    uint32_t bAddrHi[2][4], bAddrLo[2][4];
#pragma unroll
    for (int ks = 0; ks < 2; ks++)
#pragma unroll
        for (int nt = 0; nt < 4; nt++) {
            int off = (brow_base + nt * 16) * STR + ks * 16 + bkoff;
            bAddrHi[ks][nt] = smem_u32(&sWhi[off]);
            bAddrLo[ks][nt] = smem_u32(&sWlo[off]);
        }

    float acc[8][4];
#pragma unroll
    for (int i = 0; i < 8; i++)
#pragma unroll
        for (int j = 0; j < 4; j++) acc[i][j] = 0.f;

    float wreg[16];
    uint4 ahreg[2], alreg[2];

    const int nchunks = K >> 5;

    // prefetch chunk 0
    {
        if (wv) {
            const float4* p = (const float4*)(wrow);
#pragma unroll
            for (int i = 0; i < 4; i++) {
                float4 f = p[i];
                wreg[i * 4 + 0] = f.x; wreg[i * 4 + 1] = f.y;
                wreg[i * 4 + 2] = f.z; wreg[i * 4 + 3] = f.w;
            }
        } else {
#pragma unroll
            for (int i = 0; i < 16; i++) wreg[i] = 0.f;
        }
        if (do_a) {
            const uint4* ph = (const uint4*)(arow_hi);
            const uint4* pl = (const uint4*)(arow_lo);
            ahreg[0] = ph[0]; ahreg[1] = ph[1];
            alreg[0] = pl[0]; alreg[1] = pl[1];
        }
    }

    for (int ck = 0; ck < nchunks; ck++) {
        // ---- store staged regs to smem ----
        {
            int wb = r * STR + hf * 16;
#pragma unroll
            for (int q = 0; q < 2; q++) {
                uint4 hv, lv;
                float f0 = wreg[q * 8 + 0], f1 = wreg[q * 8 + 1];
                float f2 = wreg[q * 8 + 2], f3 = wreg[q * 8 + 3];
                float f4 = wreg[q * 8 + 4], f5 = wreg[q * 8 + 5];
                float f6 = wreg[q * 8 + 6], f7 = wreg[q * 8 + 7];
                float h0 = __bfloat162float(__float2bfloat16(f0));
                float h1 = __bfloat162float(__float2bfloat16(f1));
                float h2 = __bfloat162float(__float2bfloat16(f2));
                float h3 = __bfloat162float(__float2bfloat16(f3));
                float h4 = __bfloat162float(__float2bfloat16(f4));
                float h5 = __bfloat162float(__float2bfloat16(f5));
                float h6 = __bfloat162float(__float2bfloat16(f6));
                float h7 = __bfloat162float(__float2bfloat16(f7));
                hv.x = pack_bf(f0, f1); hv.y = pack_bf(f2, f3);
                hv.z = pack_bf(f4, f5); hv.w = pack_bf(f6, f7);
                lv.x = pack_bf(f0 - h0, f1 - h1); lv.y = pack_bf(f2 - h2, f3 - h3);
                lv.z = pack_bf(f4 - h4, f5 - h5); lv.w = pack_bf(f6 - h6, f7 - h7);
                *(uint4*)&sWhi[wb + q * 8] = hv;
                *(uint4*)&sWlo[wb + q * 8] = lv;
            }
            if (do_a) {
                int ab = r * STR + hf * 16;
                *(uint4*)&sAhi[ab + 0] = ahreg[0];
                *(uint4*)&sAhi[ab + 8] = ahreg[1];
                *(uint4*)&sAlo[ab + 0] = alreg[0];
                *(uint4*)&sAlo[ab + 8] = alreg[1];
            }
        }
        __syncthreads();

        // ---- prefetch next chunk while computing ----
        if (ck + 1 < nchunks) {
            if (wv) {
                const float4* p = (const float4*)(wrow + (ck + 1) * 32);
#pragma unroll
                for (int i = 0; i < 4; i++) {
                    float4 f = p[i];
                    wreg[i * 4 + 0] = f.x; wreg[i * 4 + 1] = f.y;
                    wreg[i * 4 + 2] = f.z; wreg[i * 4 + 3] = f.w;
                }
            }
            if (do_a) {
                const uint4* ph = (const uint4*)(arow_hi + (ck + 1) * 32);
                const uint4* pl = (const uint4*)(arow_lo + (ck + 1) * 32);
                ahreg[0] = ph[0]; ahreg[1] = ph[1];
                alreg[0] = pl[0]; alreg[1] = pl[1];
            }
        }

        // ---- 3-pass compute: Ahi*Whi + Ahi*Wlo + Alo*Whi ----
#pragma unroll
        for (int p = 0; p < 3; p++) {
#pragma unroll
            for (int ks = 0; ks < 2; ks++) {
                uint32_t a0, a1, a2, a3;
                ldsm_x4((p < 2) ? aAddrHi[ks] : aAddrLo[ks], a0, a1, a2, a3);
#pragma unroll
                for (int nt = 0; nt < 4; nt++) {
                    uint32_t b0, b1, b2, b3;
                    ldsm_x4((p == 1) ? bAddrLo[ks][nt] : bAddrHi[ks][nt],
                            b0, b1, b2, b3);
                    mma_bf16(acc[nt * 2], a0, a1, a2, a3, b0, b1);
                    mma_bf16(acc[nt * 2 + 1], a0, a1, a2, a3, b2, b3);
                }
            }
        }
        __syncthreads();
    }

    // ---- epilogue ----
    const int qrow = lane >> 2, qcol = (lane & 3) * 2;
    const int m0 = wr * 16 + qrow;
#pragma unroll
    for (int nt = 0; nt < 8; nt++) {
        int n = n0 + wc * 64 + nt * 8 + qcol;
        float b0v = 0.f, b1v = 0.f;
        if (bias) {
            if (n < Ntot) b0v = bias[n];
            if (n + 1 < Ntot) b1v = bias[n + 1];
        }
        if (n < Ntot) {
            C[(size_t)m0 * ldc + n] = acc[nt][0] + b0v;
            C[(size_t)(m0 + 8) * ldc + n] = acc[nt][2] + b0v;
        }
        if (n + 1 < Ntot) {
            C[(size_t)m0 * ldc + n + 1] = acc[nt][1] + b1v;
            C[(size_t)(m0 + 8) * ldc + n + 1] = acc[nt][3] + b1v;
        }
    }
}

// ================= hi/lo split prep kernels ==================================
__global__ void split_emb(const int* __restrict__ seq, const float* __restrict__ emb,
                          __nv_bfloat16* __restrict__ hi, __nv_bfloat16* __restrict__ lo) {
    int r = blockIdx.x, t = threadIdx.x;
    const float* src = emb + (size_t)seq[r] * EE;
    for (int j = t; j < 1024; j += 256) {
        float f = src[j];
        __nv_bfloat16 h = __float2bfloat16(f);
        hi[r * 1024 + j] = h;
        lo[r * 1024 + j] = __float2bfloat16(f - __bfloat162float(h));
    }
}

__global__ void split_plain(const float* __restrict__ src,
                            __nv_bfloat16* __restrict__ hi, __nv_bfloat16* __restrict__ lo) {
    int r = blockIdx.x, t = threadIdx.x;
    for (int j = t; j < 1024; j += 256) {
        float f = src[(size_t)r * 1024 + j];
        __nv_bfloat16 h = __float2bfloat16(f);
        hi[r * 1024 + j] = h;
        lo[r * 1024 + j] = __float2bfloat16(f - __bfloat162float(h));
    }
}

// ================= SIMT GEMMs (small problems) ===============================
__global__ __launch_bounds__(128)
void gemm_tn(const float* __restrict__ A, int lda,
             const float* __restrict__ W, int ldw,
             float* __restrict__ Cpart, int N, int K) {
    __shared__ float As[16][64];
    __shared__ float Ws[16][128];
    const int tid = threadIdx.x;
    const int n0 = blockIdx.x * 128;
    const int kchunk = K / gridDim.y;
    const int k0 = blockIdx.y * kchunk;
    const int tx = tid & 15, ty = tid >> 4;
    const int am = tid >> 1, akq = (tid & 1) * 8;
    const int wn = tid;
    const bool wv2 = (n0 + wn) < N;
    const float* wrow = W + (size_t)(n0 + wn) * ldw;

    float acc[8][8];
#pragma unroll
    for (int i = 0; i < 8; i++)
#pragma unroll
        for (int j = 0; j < 8; j++) acc[i][j] = 0.f;

    for (int kt = k0; kt < k0 + kchunk; kt += 16) {
        float4 a0 = *(const float4*)(A + (size_t)am * lda + kt + akq);
        float4 a1 = *(const float4*)(A + (size_t)am * lda + kt + akq + 4);
        As[akq + 0][am] = a0.x; As[akq + 1][am] = a0.y;
        As[akq + 2][am] = a0.z; As[akq + 3][am] = a0.w;
        As[akq + 4][am] = a1.x; As[akq + 5][am] = a1.y;
        As[akq + 6][am] = a1.z; As[akq + 7][am] = a1.w;
        if (wv2) {
#pragma unroll
            for (int kk = 0; kk < 16; kk += 4) {
                float4 w = *(const float4*)(wrow + kt + kk);
                Ws[kk + 0][wn] = w.x; Ws[kk + 1][wn] = w.y;
                Ws[kk + 2][wn] = w.z; Ws[kk + 3][wn] = w.w;
            }
        } else {
#pragma unroll
            for (int kk = 0; kk < 16; kk++) Ws[kk][wn] = 0.f;
        }
        __syncthreads();
#pragma unroll
        for (int k = 0; k < 16; k++) {
            float4 av0 = *(const float4*)&As[k][ty * 8];
            float4 av1 = *(const float4*)&As[k][ty * 8 + 4];
            float4 bv0 = *(const float4*)&Ws[k][tx * 8];
            float4 bv1 = *(const float4*)&Ws[k][tx * 8 + 4];
            float ar[8] = {av0.x, av0.y, av0.z, av0.w, av1.x, av1.y, av1.z, av1.w};
            float br[8] = {bv0.x, bv0.y, bv0.z, bv0.w, bv1.x, bv1.y, bv1.z, bv1.w};
#pragma unroll
            for (int i = 0; i < 8; i++)
#pragma unroll
                for (int j = 0; j < 8; j++)
                    acc[i][j] = fmaf(ar[i], br[j], acc[i][j]);
        }
        __syncthreads();
    }
    float* P = Cpart + (size_t)blockIdx.y * 64 * (size_t)N;
#pragma unroll
    for (int i = 0; i < 8; i++) {
        int m = ty * 8 + i;
#pragma unroll
        for (int j = 0; j < 8; j++) {
            int c = n0 + tx * 8 + j;
            if (c < N) P[(size_t)m * N + c] = acc[i][j];
        }
    }
}

__global__ __launch_bounds__(128)
void gemm_nn(const float* __restrict__ A, int lda,
             const float* __restrict__ W, int ldw,
             float* __restrict__ Cpart, int N, int K) {
    __shared__ float As[16][64];
    __shared__ float Ws[16][128];
    const int tid = threadIdx.x;
    const int n0 = blockIdx.x * 128;
    const int kchunk = K / gridDim.y;
    const int k0 = blockIdx.y * kchunk;
    const int tx = tid & 15, ty = tid >> 4;
    const int am = tid >> 1, akq = (tid & 1) * 8;
    const int wk = tid >> 3, wnq = (tid & 7) * 16;

    float acc[8][8];
#pragma unroll
    for (int i = 0; i < 8; i++)
#pragma unroll
        for (int j = 0; j < 8; j++) acc[i][j] = 0.f;

    for (int kt = k0; kt < k0 + kchunk; kt += 16) {
        float4 a0 = *(const float4*)(A + (size_t)am * lda + kt + akq);
        float4 a1 = *(const float4*)(A + (size_t)am * lda + kt + akq + 4);
        As[akq + 0][am] = a0.x; As[akq + 1][am] = a0.y;
        As[akq + 2][am] = a0.z; As[akq + 3][am] = a0.w;
        As[akq + 4][am] = a1.x; As[akq + 5][am] = a1.y;
        As[akq + 6][am] = a1.z; As[akq + 7][am] = a1.w;
#pragma unroll
        for (int q = 0; q < 4; q++) {
            int n = n0 + wnq + q * 4;
            float4 w;
            if (n + 3 < N) w = *(const float4*)(W + (size_t)(kt + wk) * ldw + n);
            else w = make_float4(0.f, 0.f, 0.f, 0.f);
            Ws[wk][wnq + q * 4 + 0] = w.x; Ws[wk][wnq + q * 4 + 1] = w.y;
            Ws[wk][wnq + q * 4 + 2] = w.z; Ws[wk][wnq + q * 4 + 3] = w.w;
        }
        __syncthreads();
#pragma unroll
        for (int k = 0; k < 16; k++) {
            float4 av0 = *(const float4*)&As[k][ty * 8];
            float4 av1 = *(const float4*)&As[k][ty * 8 + 4];
            float4 bv0 = *(const float4*)&Ws[k][tx * 8];
            float4 bv1 = *(const float4*)&Ws[k][tx * 8 + 4];
            float ar[8] = {av0.x, av0.y, av0.z, av0.w, av1.x, av1.y, av1.z, av1.w};
            float br[8] = {bv0.x, bv0.y, bv0.z, bv0.w, bv1.x, bv1.y, bv1.z, bv1.w};
#pragma unroll
            for (int i = 0; i < 8; i++)
#pragma unroll
                for (int j = 0; j < 8; j++)
                    acc[i][j] = fmaf(ar[i], br[j], acc[i][j]);
        }
        __syncthreads();
    }
    float* P = Cpart + (size_t)blockIdx.y * 64 * (size_t)N;
#pragma unroll
    for (int i = 0; i < 8; i++) {
        int m = ty * 8 + i;
#pragma unroll
        for (int j = 0; j < 8; j++) {
            int c = n0 + tx * 8 + j;
            if (c < N) P[(size_t)m * N + c] = acc[i][j];
        }
    }
}

__global__ void reduce_ba(const float* __restrict__ P, int nsplit, int ntot,
                          int N, const float* __restrict__ bias,
                          float* __restrict__ C, int act) {
    int idx = blockIdx.x * blockDim.x + threadIdx.x;
    if (idx >= ntot) return;
    float s = 0.f;
    for (int p = 0; p < nsplit; p++) s += P[(size_t)p * ntot + idx];
    if (bias) s += bias[idx % N];
    if (act) s = tanhf(s);
    C[idx] = s;
}

// ================= pointwise / attention kernels =============================
__global__ void gru_combine(const float* __restrict__ gi,
                            const float* __restrict__ gh,
                            const float* __restrict__ b_ih,
                            const float* __restrict__ b_hh,
                            const float* __restrict__ hprev,
                            float* __restrict__ cat,
                            float* __restrict__ out_hidden) {
    int idx = blockIdx.x * blockDim.x + threadIdx.x;  // 65536
    int b = idx >> 10, j = idx & 1023;
    size_t base = (size_t)b * H3 + j;
    float ir = gi[base] + b_ih[j];
    float iz = gi[base + HH] + b_ih[HH + j];
    float in_ = gi[base + 2 * HH] + b_ih[2 * HH + j];
    float hr = gh[base] + b_hh[j];
    float hz = gh[base + HH] + b_hh[HH + j];
    float hn = gh[base + 2 * HH] + b_hh[2 * HH + j];
    float r = 1.f / (1.f + expf(-(ir + hr)));
    float z = 1.f / (1.f + expf(-(iz + hz)));
    float n = tanhf(in_ + r * hn);
    float hp = hprev[(size_t)b * HH + j];
    float hnew = (1.f - z) * n + z * hp;
    cat[(size_t)b * 2048 + j] = hnew;
    out_hidden[idx] = hnew;
}

__global__ void hb_kernel(const float* __restrict__ cat,
                          const float* __restrict__ attn_b,
                          float* __restrict__ hb) {
    int b = blockIdx.x, t = threadIdx.x;
    __shared__ float sm[256];
    float s = 0.f;
#pragma unroll
    for (int i = 0; i < 4; i++) {
        int j = t + 256 * i;
        s += cat[(size_t)b * 2048 + j] * attn_b[j];
    }
    sm[t] = s;
    __syncthreads();
    for (int st = 128; st > 0; st >>= 1) {
        if (t < st) sm[t] += sm[t + st];
        __syncthreads();
    }
    if (t == 0) hb[b] = sm[0];
}

__global__ void scores_kernel(const float* __restrict__ q,
                              const float* __restrict__ enc,
                              const float* __restrict__ hb,
                              float* __restrict__ scores) {
    int pair = blockIdx.x * 8 + (threadIdx.x >> 5);
    int lane = threadIdx.x & 31;
    int b = pair >> 8, l = pair & 255;
    const float* e = enc + ((size_t)l * BB + b) * HH;
    const float* qr = q + (size_t)b * HH;
    float s = 0.f;
#pragma unroll
    for (int i = 0; i < 8; i++) {
        int h = lane * 4 + i * 128;
        float4 ev = *(const float4*)(e + h);
        float4 qv = *(const float4*)(qr + h);
        s += ev.x * qv.x + ev.y * qv.y + ev.z * qv.z + ev.w * qv.w;
    }
#pragma unroll
    for (int o = 16; o > 0; o >>= 1) s += __shfl_xor_sync(0xffffffffu, s, o);
    if (lane == 0) scores[(size_t)b * LL + l] = s + hb[b];
}

__global__ void softmax_kernel(const float* __restrict__ scores,
                               float* __restrict__ aw,
                               float* __restrict__ out_attn) {
    int b = blockIdx.x, t = threadIdx.x;
    __shared__ float sm[256];
    float v = scores[(size_t)b * LL + t];
    sm[t] = v;
    __syncthreads();
    for (int s = 128; s > 0; s >>= 1) {
        if (t < s) sm[t] = fmaxf(sm[t], sm[t + s]);
        __syncthreads();
    }
    float mx = sm[0];
    __syncthreads();
    float e = expf(v - mx);
    sm[t] = e;
    __syncthreads();
    for (int s = 128; s > 0; s >>= 1) {
        if (t < s) sm[t] += sm[t + s];
        __syncthreads();
    }
    float w = e / sm[0];
    aw[(size_t)b * LL + t] = w;
    out_attn[(size_t)b * LL + t] = w;
}

__global__ void context_kernel(const float* __restrict__ aw,
                               const float* __restrict__ enc,
                               float* __restrict__ cat) {
    int b = blockIdx.x;
    int hc = blockIdx.y * 128 + threadIdx.x;
    __shared__ float aws[256];
    if (threadIdx.x < 128) {
        aws[threadIdx.x] = aw[(size_t)b * LL + threadIdx.x];
        aws[threadIdx.x + 128] = aw[(size_t)b * LL + 128 + threadIdx.x];
    }
    __syncthreads();
    float acc = 0.f;
    const float* e = enc + (size_t)b * HH + hc;
#pragma unroll 4
    for (int l = 0; l < LL; l++) acc += aws[l] * e[(size_t)l * BB * HH];
    cat[(size_t)b * 2048 + 1024 + hc] = acc;
}

// ================= launch =====================================================
extern "C" void kernel_launch(void* const* d_in, const int* in_sizes, int n_in,
                              void* d_out, int out_size) {
    const int*   seq  = (const int*)d_in[0];
    const float* h0   = (const float*)d_in[1];
    const float* enc  = (const float*)d_in[2];
    const float* emb  = (const float*)d_in[3];
    const float* w_ih = (const float*)d_in[4];
    const float* w_hh = (const float*)d_in[5];
    const float* b_ih = (const float*)d_in[6];
    const float* b_hh = (const float*)d_in[7];
    const float* attw = (const float*)d_in[8];
    const float* attb = (const float*)d_in[9];
    const float* cw   = (const float*)d_in[10];
    const float* cb   = (const float*)d_in[11];
    const float* ow   = (const float*)d_in[12];
    const float* ob   = (const float*)d_in[13];

    float* out        = (float*)d_out;                  // [B, V]
    float* out_hidden = out + (size_t)BB * VV;          // [B, H]
    float* out_attn   = out_hidden + (size_t)BB * HH;   // [B, L]

    __nv_bfloat16 *xhi, *xlo, *hhi, *hlo, *chi, *clo;
    float *gi, *gh, *cat, *hb, *q, *qp, *sc, *aw, *cp, *co;
    cudaGetSymbolAddress((void**)&xhi, g_xhi);
    cudaGetSymbolAddress((void**)&xlo, g_xlo);
    cudaGetSymbolAddress((void**)&hhi, g_hhi);
    cudaGetSymbolAddress((void**)&hlo, g_hlo);
    cudaGetSymbolAddress((void**)&chi, g_chi);
    cudaGetSymbolAddress((void**)&clo, g_clo);
    cudaGetSymbolAddress((void**)&gi, g_gi);
    cudaGetSymbolAddress((void**)&gh, g_gh);
    cudaGetSymbolAddress((void**)&cat, g_cat);
    cudaGetSymbolAddress((void**)&hb, g_hb);
    cudaGetSymbolAddress((void**)&q, g_q);
    cudaGetSymbolAddress((void**)&qp, g_qpart);
    cudaGetSymbolAddress((void**)&sc, g_scores);
    cudaGetSymbolAddress((void**)&aw, g_aw);
    cudaGetSymbolAddress((void**)&cp, g_cpart);
    cudaGetSymbolAddress((void**)&co, g_co);

    // 1) hi/lo splits of embeddings (with gather) and h0
    split_emb<<<BB, 256>>>(seq, emb, xhi, xlo);
    split_plain<<<BB, 256>>>(h0, hhi, hlo);

    // 2) GRU gate GEMMs on tensor cores (both problems in one grid)
    hmma_gemm<<<dim3(24, 2), 256>>>(xhi, xlo, w_ih, gi,
                                    hhi, hlo, w_hh, gh,
                                    nullptr, H3, EE, H3);

    // 3) combine gates -> h_new (writes hidden output and cat rows)
    gru_combine<<<256, 256>>>(gi, gh, b_ih, b_hh, h0, cat, out_hidden);

    // 4) hb = h_new . attn_b
    hb_kernel<<<BB, 256>>>(cat, attb, hb);

    // 5) q = h_new @ attn_w  (SIMT, split-K=16 + reduce)
    gemm_nn<<<dim3(8, 16), 128>>>(cat, 2048, attw, HH, qp, HH, HH);
    reduce_ba<<<(BB * HH) / 256, 256>>>(qp, 16, BB * HH, HH, nullptr, q, 0);

    // 6) scores = q . enc + hb ; softmax ; context
    scores_kernel<<<2048, 256>>>(q, enc, hb, sc);
    softmax_kernel<<<BB, 256>>>(sc, aw, out_attn);
    context_kernel<<<dim3(BB, 8), 128>>>(aw, enc, cat);

    // 7) concat_out = tanh([h_new|context] @ concat_w^T + concat_b)
    gemm_tn<<<dim3(8, 16), 128>>>(cat, 2048, cw, 2048, cp, HH, 2048);
    reduce_ba<<<(BB * HH) / 256, 256>>>(cp, 16, BB * HH, HH, cb, co, 1);

    // 8) split concat_out, then the big V-GEMM on tensor cores
    split_plain<<<BB, 256>>>(co, chi, clo);
    hmma_gemm<<<dim3((VV + 127) / 128, 1), 256>>>(
        chi, clo, ow, out, chi, clo, ow, out, ob, VV, HH, VV);
}

// round 4
// speedup vs baseline: 2.0083x; 1.3823x over previous
#include <cuda_runtime.h>
#include <cuda_bf16.h>
#include <math.h>
#include <stdint.h>

#define BB 64
#define LL 256
#define HH 1024
#define EE 1024
#define VV 50257
#define H3 3072

// ================= scratch (__device__ globals) =============================
__device__ __align__(16) __nv_bfloat16 g_xhi[BB * 1024];
__device__ __align__(16) __nv_bfloat16 g_xlo[BB * 1024];
__device__ __align__(16) __nv_bfloat16 g_hhi[BB * 1024];
__device__ __align__(16) __nv_bfloat16 g_hlo[BB * 1024];
__device__ __align__(16) __nv_bfloat16 g_chi[BB * 1024];
__device__ __align__(16) __nv_bfloat16 g_clo[BB * 1024];
__device__ float g_gi[2 * BB * H3];            // k-split partials
__device__ float g_gh[2 * BB * H3];
__device__ float g_cat[BB * 2 * HH];
__device__ float g_hb[BB];
__device__ float g_q[BB * HH];
__device__ float g_qpart[16 * BB * HH];
__device__ float g_scores[BB * LL];
__device__ float g_aw[BB * LL];
__device__ float g_cpart[16 * BB * HH];

// ================= helpers ===================================================
__device__ __forceinline__ uint32_t smem_u32(const void* p) {
    uint32_t a;
    asm("{ .reg .u64 t; cvta.to.shared.u64 t, %1; cvt.u32.u64 %0, t; }"
        : "=r"(a) : "l"(p));
    return a;
}

__device__ __forceinline__ void ldsm_x4(uint32_t addr, uint32_t& d0, uint32_t& d1,
                                        uint32_t& d2, uint32_t& d3) {
    asm volatile("ldmatrix.sync.aligned.m8n8.x4.shared.b16 {%0,%1,%2,%3}, [%4];"
                 : "=r"(d0), "=r"(d1), "=r"(d2), "=r"(d3) : "r"(addr));
}

__device__ __forceinline__ void mma_bf16(float* c, uint32_t a0, uint32_t a1,
                                         uint32_t a2, uint32_t a3,
                                         uint32_t b0, uint32_t b1) {
    asm volatile(
        "mma.sync.aligned.m16n8k16.row.col.f32.bf16.bf16.f32 "
        "{%0,%1,%2,%3}, {%4,%5,%6,%7}, {%8,%9}, {%0,%1,%2,%3};"
        : "+f"(c[0]), "+f"(c[1]), "+f"(c[2]), "+f"(c[3])
        : "r"(a0), "r"(a1), "r"(a2), "r"(a3), "r"(b0), "r"(b1));
}

__device__ __forceinline__ uint32_t pack_bf(float a, float b) {
    __nv_bfloat162 t = __floats2bfloat162_rn(a, b);
    return *reinterpret_cast<uint32_t*>(&t);
}

// ================= fused-convert HMMA GEMM ===================================
// C[64, n] = sum_k fp32(A[64,k]) * W[n,k]  (+bias), bf16 hi/lo 3-pass.
// A precomputed hi/lo bf16 [64, K]. W fp32 [Ntot, K] row-major, converted
// in-register while streaming (read exactly once).
// Block tile 64x128, 256 threads (8 warps of 16x64). K chunk = 32.
// gridDim.z = split-K; partial z goes to C + z*pstride (bias only if pstride==0).
#define STR 40  // smem row stride in bf16 elems (80B, conflict-free ldmatrix)

__global__ __launch_bounds__(256, 2)
void hmma_gemm(const __nv_bfloat16* __restrict__ Ahi0, const __nv_bfloat16* __restrict__ Alo0,
               const float* __restrict__ W0, float* __restrict__ C0,
               const __nv_bfloat16* __restrict__ Ahi1, const __nv_bfloat16* __restrict__ Alo1,
               const float* __restrict__ W1, float* __restrict__ C1,
               const float* __restrict__ bias, int Ntot, int K, int ldc,
               long pstride) {
    __shared__ __nv_bfloat16 sAhi[64 * STR];
    __shared__ __nv_bfloat16 sAlo[64 * STR];
    __shared__ __nv_bfloat16 sWhi[128 * STR];
    __shared__ __nv_bfloat16 sWlo[128 * STR];

    const __nv_bfloat16* Ahi = blockIdx.y ? Ahi1 : Ahi0;
    const __nv_bfloat16* Alo = blockIdx.y ? Alo1 : Alo0;
    const float* W = blockIdx.y ? W1 : W0;
    float* C = (blockIdx.y ? C1 : C0) + (size_t)blockIdx.z * pstride;

    const int tid = threadIdx.x, wid = tid >> 5, lane = tid & 31;
    const int wr = wid & 3, wc = wid >> 2;
    const int n0 = blockIdx.x * 128;

    const int kper = K / gridDim.z;
    const int koff = blockIdx.z * kper;

    // staging ids
    const int r = tid >> 1, hf = tid & 1;
    const bool wv = (n0 + r) < Ntot;
    const float* wrow = W + (size_t)(n0 + r) * K + koff + hf * 16;
    const __nv_bfloat16* arow_hi = Ahi + (size_t)(r & 63) * K + koff + hf * 16;
    const __nv_bfloat16* arow_lo = Alo + (size_t)(r & 63) * K + koff + hf * 16;
    const bool do_a = (tid < 128);

    // ldmatrix base addresses
    const int am = lane >> 3, aln = lane & 7;
    const int arow2 = wr * 16 + aln + (am & 1) * 8;
    const int akoff = (am >> 1) * 8;
    const uint32_t aHiB = smem_u32(&sAhi[arow2 * STR + akoff]);
    const uint32_t aLoB = smem_u32(&sAlo[arow2 * STR + akoff]);
    const int brow_base = wc * 64 + aln + (am >> 1) * 8;
    const int bkoff = (am & 1) * 8;
    const uint32_t bHiB = smem_u32(&sWhi[brow_base * STR + bkoff]);
    const uint32_t bLoB = smem_u32(&sWlo[brow_base * STR + bkoff]);

    float acc[8][4];
#pragma unroll
    for (int i = 0; i < 8; i++)
#pragma unroll
        for (int j = 0; j < 4; j++) acc[i][j] = 0.f;

    float wreg[16];
    uint4 ahreg[2], alreg[2];

    const int nchunks = kper >> 5;

    // prefetch chunk 0
    if (wv) {
        const float4* p = (const float4*)(wrow);
#pragma unroll
        for (int i = 0; i < 4; i++) {
            float4 f = p[i];
            wreg[i * 4 + 0] = f.x; wreg[i * 4 + 1] = f.y;
            wreg[i * 4 + 2] = f.z; wreg[i * 4 + 3] = f.w;
        }
    } else {
#pragma unroll
        for (int i = 0; i < 16; i++) wreg[i] = 0.f;
    }
    if (do_a) {
        const uint4* ph = (const uint4*)(arow_hi);
        const uint4* pl = (const uint4*)(arow_lo);
        ahreg[0] = ph[0]; ahreg[1] = ph[1];
        alreg[0] = pl[0]; alreg[1] = pl[1];
    }

    for (int ck = 0; ck < nchunks; ck++) {
        // ---- stage to smem (fp32 -> bf16 hi/lo for W) ----
        {
            int wb = r * STR + hf * 16;
#pragma unroll
            for (int q = 0; q < 2; q++) {
                uint4 hv, lv;
                float f0 = wreg[q * 8 + 0], f1 = wreg[q * 8 + 1];
                float f2 = wreg[q * 8 + 2], f3 = wreg[q * 8 + 3];
                float f4 = wreg[q * 8 + 4], f5 = wreg[q * 8 + 5];
                float f6 = wreg[q * 8 + 6], f7 = wreg[q * 8 + 7];
                float h0 = __bfloat162float(__float2bfloat16(f0));
                float h1 = __bfloat162float(__float2bfloat16(f1));
                float h2 = __bfloat162float(__float2bfloat16(f2));
                float h3 = __bfloat162float(__float2bfloat16(f3));
                float h4 = __bfloat162float(__float2bfloat16(f4));
                float h5 = __bfloat162float(__float2bfloat16(f5));
                float h6 = __bfloat162float(__float2bfloat16(f6));
                float h7 = __bfloat162float(__float2bfloat16(f7));
                hv.x = pack_bf(f0, f1); hv.y = pack_bf(f2, f3);
                hv.z = pack_bf(f4, f5); hv.w = pack_bf(f6, f7);
                lv.x = pack_bf(f0 - h0, f1 - h1); lv.y = pack_bf(f2 - h2, f3 - h3);
                lv.z = pack_bf(f4 - h4, f5 - h5); lv.w = pack_bf(f6 - h6, f7 - h7);
                *(uint4*)&sWhi[wb + q * 8] = hv;
                *(uint4*)&sWlo[wb + q * 8] = lv;
            }
            if (do_a) {
                int ab = r * STR + hf * 16;
                *(uint4*)&sAhi[ab + 0] = ahreg[0];
                *(uint4*)&sAhi[ab + 8] = ahreg[1];
                *(uint4*)&sAlo[ab + 0] = alreg[0];
                *(uint4*)&sAlo[ab + 8] = alreg[1];
            }
        }
        __syncthreads();

        // ---- prefetch next chunk ----
        if (ck + 1 < nchunks) {
            if (wv) {
                const float4* p = (const float4*)(wrow + (ck + 1) * 32);
#pragma unroll
                for (int i = 0; i < 4; i++) {
                    float4 f = p[i];
                    wreg[i * 4 + 0] = f.x; wreg[i * 4 + 1] = f.y;
                    wreg[i * 4 + 2] = f.z; wreg[i * 4 + 3] = f.w;
                }
            }
            if (do_a) {
                const uint4* ph = (const uint4*)(arow_hi + (ck + 1) * 32);
                const uint4* pl = (const uint4*)(arow_lo + (ck + 1) * 32);
                ahreg[0] = ph[0]; ahreg[1] = ph[1];
                alreg[0] = pl[0]; alreg[1] = pl[1];
            }
        }

        // ---- compute: register-cached fragments, 3 logical passes ----
#pragma unroll
        for (int ks = 0; ks < 2; ks++) {
            uint32_t ah0, ah1, ah2, ah3, al0, al1, al2, al3;
            ldsm_x4(aHiB + ks * 32, ah0, ah1, ah2, ah3);
            ldsm_x4(aLoB + ks * 32, al0, al1, al2, al3);
#pragma unroll
            for (int nt = 0; nt < 4; nt++) {
                const uint32_t off = nt * (16 * STR * 2) + ks * 32;
                uint32_t bh0, bh1, bh2, bh3, bl0, bl1, bl2, bl3;
                ldsm_x4(bHiB + off, bh0, bh1, bh2, bh3);
                ldsm_x4(bLoB + off, bl0, bl1, bl2, bl3);
                mma_bf16(acc[nt * 2],     ah0, ah1, ah2, ah3, bh0, bh1);
                mma_bf16(acc[nt * 2 + 1], ah0, ah1, ah2, ah3, bh2, bh3);
                mma_bf16(acc[nt * 2],     ah0, ah1, ah2, ah3, bl0, bl1);
                mma_bf16(acc[nt * 2 + 1], ah0, ah1, ah2, ah3, bl2, bl3);
                mma_bf16(acc[nt * 2],     al0, al1, al2, al3, bh0, bh1);
                mma_bf16(acc[nt * 2 + 1], al0, al1, al2, al3, bh2, bh3);
            }
        }
        __syncthreads();
    }

    // ---- epilogue ----
    const int qrow = lane >> 2, qcol = (lane & 3) * 2;
    const int m0 = wr * 16 + qrow;
    const bool use_bias = (bias != nullptr) && (pstride == 0);
#pragma unroll
    for (int nt = 0; nt < 8; nt++) {
        int n = n0 + wc * 64 + nt * 8 + qcol;
        float b0v = 0.f, b1v = 0.f;
        if (use_bias) {
            if (n < Ntot) b0v = bias[n];
            if (n + 1 < Ntot) b1v = bias[n + 1];
        }
        if (n < Ntot) {
            C[(size_t)m0 * ldc + n] = acc[nt][0] + b0v;
            C[(size_t)(m0 + 8) * ldc + n] = acc[nt][2] + b0v;
        }
        if (n + 1 < Ntot) {
            C[(size_t)m0 * ldc + n + 1] = acc[nt][1] + b1v;
            C[(size_t)(m0 + 8) * ldc + n + 1] = acc[nt][3] + b1v;
        }
    }
}

// ================= fused hi/lo split prep (emb gather + h0) ==================
__global__ void split_all(const int* __restrict__ seq, const float* __restrict__ emb,
                          const float* __restrict__ h0,
                          __nv_bfloat16* __restrict__ xhi, __nv_bfloat16* __restrict__ xlo,
                          __nv_bfloat16* __restrict__ hhi, __nv_bfloat16* __restrict__ hlo) {
    int r = blockIdx.x, t = threadIdx.x;
    const float* src;
    __nv_bfloat16 *hi, *lo;
    int row;
    if (r < BB) {
        src = emb + (size_t)seq[r] * EE; hi = xhi; lo = xlo; row = r;
    } else {
        row = r - BB;
        src = h0 + (size_t)row * HH; hi = hhi; lo = hlo;
    }
    for (int j = t; j < 1024; j += 256) {
        float f = src[j];
        __nv_bfloat16 h = __float2bfloat16(f);
        hi[row * 1024 + j] = h;
        lo[row * 1024 + j] = __float2bfloat16(f - __bfloat162float(h));
    }
}

// ================= SIMT GEMMs (small problems) ===============================
__global__ __launch_bounds__(128)
void gemm_tn(const float* __restrict__ A, int lda,
             const float* __restrict__ W, int ldw,
             float* __restrict__ Cpart, int N, int K) {
    __shared__ float As[16][64];
    __shared__ float Ws[16][128];
    const int tid = threadIdx.x;
    const int n0 = blockIdx.x * 128;
    const int kchunk = K / gridDim.y;
    const int k0 = blockIdx.y * kchunk;
    const int tx = tid & 15, ty = tid >> 4;
    const int am = tid >> 1, akq = (tid & 1) * 8;
    const int wn = tid;
    const bool wv2 = (n0 + wn) < N;
    const float* wrow = W + (size_t)(n0 + wn) * ldw;

    float acc[8][8];
#pragma unroll
    for (int i = 0; i < 8; i++)
#pragma unroll
        for (int j = 0; j < 8; j++) acc[i][j] = 0.f;

    for (int kt = k0; kt < k0 + kchunk; kt += 16) {
        float4 a0 = *(const float4*)(A + (size_t)am * lda + kt + akq);
        float4 a1 = *(const float4*)(A + (size_t)am * lda + kt + akq + 4);
        As[akq + 0][am] = a0.x; As[akq + 1][am] = a0.y;
        As[akq + 2][am] = a0.z; As[akq + 3][am] = a0.w;
        As[akq + 4][am] = a1.x; As[akq + 5][am] = a1.y;
        As[akq + 6][am] = a1.z; As[akq + 7][am] = a1.w;
        if (wv2) {
#pragma unroll
            for (int kk = 0; kk < 16; kk += 4) {
                float4 w = *(const float4*)(wrow + kt + kk);
                Ws[kk + 0][wn] = w.x; Ws[kk + 1][wn] = w.y;
                Ws[kk + 2][wn] = w.z; Ws[kk + 3][wn] = w.w;
            }
        } else {
#pragma unroll
            for (int kk = 0; kk < 16; kk++) Ws[kk][wn] = 0.f;
        }
        __syncthreads();
#pragma unroll
        for (int k = 0; k < 16; k++) {
            float4 av0 = *(const float4*)&As[k][ty * 8];
            float4 av1 = *(const float4*)&As[k][ty * 8 + 4];
            float4 bv0 = *(const float4*)&Ws[k][tx * 8];
            float4 bv1 = *(const float4*)&Ws[k][tx * 8 + 4];
            float ar[8] = {av0.x, av0.y, av0.z, av0.w, av1.x, av1.y, av1.z, av1.w};
            float br[8] = {bv0.x, bv0.y, bv0.z, bv0.w, bv1.x, bv1.y, bv1.z, bv1.w};
#pragma unroll
            for (int i = 0; i < 8; i++)
#pragma unroll
                for (int j = 0; j < 8; j++)
                    acc[i][j] = fmaf(ar[i], br[j], acc[i][j]);
        }
        __syncthreads();
    }
    float* P = Cpart + (size_t)blockIdx.y * 64 * (size_t)N;
#pragma unroll
    for (int i = 0; i < 8; i++) {
        int m = ty * 8 + i;
#pragma unroll
        for (int j = 0; j < 8; j++) {
            int c = n0 + tx * 8 + j;
            if (c < N) P[(size_t)m * N + c] = acc[i][j];
        }
    }
}

__global__ __launch_bounds__(128)
void gemm_nn(const float* __restrict__ A, int lda,
             const float* __restrict__ W, int ldw,
             float* __restrict__ Cpart, int N, int K) {
    __shared__ float As[16][64];
    __shared__ float Ws[16][128];
    const int tid = threadIdx.x;
    const int n0 = blockIdx.x * 128;
    const int kchunk = K / gridDim.y;
    const int k0 = blockIdx.y * kchunk;
    const int tx = tid & 15, ty = tid >> 4;
    const int am = tid >> 1, akq = (tid & 1) * 8;
    const int wk = tid >> 3, wnq = (tid & 7) * 16;

    float acc[8][8];
#pragma unroll
    for (int i = 0; i < 8; i++)
#pragma unroll
        for (int j = 0; j < 8; j++) acc[i][j] = 0.f;

    for (int kt = k0; kt < k0 + kchunk; kt += 16) {
        float4 a0 = *(const float4*)(A + (size_t)am * lda + kt + akq);
        float4 a1 = *(const float4*)(A + (size_t)am * lda + kt + akq + 4);
        As[akq + 0][am] = a0.x; As[akq + 1][am] = a0.y;
        As[akq + 2][am] = a0.z; As[akq + 3][am] = a0.w;
        As[akq + 4][am] = a1.x; As[akq + 5][am] = a1.y;
        As[akq + 6][am] = a1.z; As[akq + 7][am] = a1.w;
#pragma unroll
        for (int q = 0; q < 4; q++) {
            int n = n0 + wnq + q * 4;
            float4 w;
            if (n + 3 < N) w = *(const float4*)(W + (size_t)(kt + wk) * ldw + n);
            else w = make_float4(0.f, 0.f, 0.f, 0.f);
            Ws[wk][wnq + q * 4 + 0] = w.x; Ws[wk][wnq + q * 4 + 1] = w.y;
            Ws[wk][wnq + q * 4 + 2] = w.z; Ws[wk][wnq + q * 4 + 3] = w.w;
        }
        __syncthreads();
#pragma unroll
        for (int k = 0; k < 16; k++) {
            float4 av0 = *(const float4*)&As[k][ty * 8];
            float4 av1 = *(const float4*)&As[k][ty * 8 + 4];
            float4 bv0 = *(const float4*)&Ws[k][tx * 8];
            float4 bv1 = *(const float4*)&Ws[k][tx * 8 + 4];
            float ar[8] = {av0.x, av0.y, av0.z, av0.w, av1.x, av1.y, av1.z, av1.w};
            float br[8] = {bv0.x, bv0.y, bv0.z, bv0.w, bv1.x, bv1.y, bv1.z, bv1.w};
#pragma unroll
            for (int i = 0; i < 8; i++)
#pragma unroll
                for (int j = 0; j < 8; j++)
                    acc[i][j] = fmaf(ar[i], br[j], acc[i][j]);
        }
        __syncthreads();
    }
    float* P = Cpart + (size_t)blockIdx.y * 64 * (size_t)N;
#pragma unroll
    for (int i = 0; i < 8; i++) {
        int m = ty * 8 + i;
#pragma unroll
        for (int j = 0; j < 8; j++) {
            int c = n0 + tx * 8 + j;
            if (c < N) P[(size_t)m * N + c] = acc[i][j];
        }
    }
}

__global__ void reduce_ba(const float* __restrict__ P, int nsplit, int ntot,
                          int N, const float* __restrict__ bias,
                          float* __restrict__ C, int act) {
    int idx = blockIdx.x * blockDim.x + threadIdx.x;
    if (idx >= ntot) return;
    float s = 0.f;
    for (int p = 0; p < nsplit; p++) s += P[(size_t)p * ntot + idx];
    if (bias) s += bias[idx % N];
    if (act) s = tanhf(s);
    C[idx] = s;
}

// reduce 16 partials + bias + tanh + hi/lo split (for the V-GEMM's A)
__global__ void reduce_tanh_split(const float* __restrict__ P,
                                  const float* __restrict__ bias,
                                  __nv_bfloat16* __restrict__ hi,
                                  __nv_bfloat16* __restrict__ lo) {
    int idx = blockIdx.x * blockDim.x + threadIdx.x;  // 65536
    float s = 0.f;
#pragma unroll
    for (int p = 0; p < 16; p++) s += P[(size_t)p * (BB * HH) + idx];
    s = tanhf(s + bias[idx & 1023]);
    __nv_bfloat16 h = __float2bfloat16(s);
    hi[idx] = h;
    lo[idx] = __float2bfloat16(s - __bfloat162float(h));
}

// ================= fused GRU combine + hb reduction ==========================
__global__ void gru_combine_hb(const float* __restrict__ gi,
                               const float* __restrict__ gh,
                               const float* __restrict__ b_ih,
                               const float* __restrict__ b_hh,
                               const float* __restrict__ hprev,
                               const float* __restrict__ attn_b,
                               float* __restrict__ cat,
                               float* __restrict__ out_hidden,
                               float* __restrict__ hb) {
    int b = blockIdx.x, t = threadIdx.x;
    const int P = BB * H3;
    float hb_acc = 0.f;
#pragma unroll
    for (int ii = 0; ii < 4; ii++) {
        int j = t + ii * 256;
        size_t base = (size_t)b * H3 + j;
        float ir = gi[base] + gi[P + base] + b_ih[j];
        float iz = gi[base + HH] + gi[P + base + HH] + b_ih[HH + j];
        float in_ = gi[base + 2 * HH] + gi[P + base + 2 * HH] + b_ih[2 * HH + j];
        float hr = gh[base] + gh[P + base] + b_hh[j];
        float hz = gh[base + HH] + gh[P + base + HH] + b_hh[HH + j];
        float hn = gh[base + 2 * HH] + gh[P + base + 2 * HH] + b_hh[2 * HH + j];
        float r = 1.f / (1.f + expf(-(ir + hr)));
        float z = 1.f / (1.f + expf(-(iz + hz)));
        float n = tanhf(in_ + r * hn);
        float hp = hprev[(size_t)b * HH + j];
        float hnew = (1.f - z) * n + z * hp;
        cat[(size_t)b * 2048 + j] = hnew;
        out_hidden[(size_t)b * HH + j] = hnew;
        hb_acc += hnew * attn_b[j];
    }
    __shared__ float sm[256];
    sm[t] = hb_acc;
    __syncthreads();
    for (int st = 128; st > 0; st >>= 1) {
        if (t < st) sm[t] += sm[t + st];
        __syncthreads();
    }
    if (t == 0) hb[b] = sm[0];
}

// ================= attention kernels =========================================
__global__ void scores_kernel(const float* __restrict__ q,
                              const float* __restrict__ enc,
                              const float* __restrict__ hb,
                              float* __restrict__ scores) {
    int pair = blockIdx.x * 8 + (threadIdx.x >> 5);
    int lane = threadIdx.x & 31;
    int b = pair >> 8, l = pair & 255;
    const float* e = enc + ((size_t)l * BB + b) * HH;
    const float* qr = q + (size_t)b * HH;
    float s = 0.f;
#pragma unroll
    for (int i = 0; i < 8; i++) {
        int h = lane * 4 + i * 128;
        float4 ev = *(const float4*)(e + h);
        float4 qv = *(const float4*)(qr + h);
        s += ev.x * qv.x + ev.y * qv.y + ev.z * qv.z + ev.w * qv.w;
    }
#pragma unroll
    for (int o = 16; o > 0; o >>= 1) s += __shfl_xor_sync(0xffffffffu, s, o);
    if (lane == 0) scores[(size_t)b * LL + l] = s + hb[b];
}

__global__ void softmax_kernel(const float* __restrict__ scores,
                               float* __restrict__ aw,
                               float* __restrict__ out_attn) {
    int b = blockIdx.x, t = threadIdx.x;
    __shared__ float sm[256];
    float v = scores[(size_t)b * LL + t];
    sm[t] = v;
    __syncthreads();
    for (int s = 128; s > 0; s >>= 1) {
        if (t < s) sm[t] = fmaxf(sm[t], sm[t + s]);
        __syncthreads();
    }
    float mx = sm[0];
    __syncthreads();
    float e = expf(v - mx);
    sm[t] = e;
    __syncthreads();
    for (int s = 128; s > 0; s >>= 1) {
        if (t < s) sm[t] += sm[t + s];
        __syncthreads();
    }
    float w = e / sm[0];
    aw[(size_t)b * LL + t] = w;
    out_attn[(size_t)b * LL + t] = w;
}

__global__ void context_kernel(const float* __restrict__ aw,
                               const float* __restrict__ enc,
                               float* __restrict__ cat) {
    int b = blockIdx.x;
    int hc = blockIdx.y * 128 + threadIdx.x;
    __shared__ float aws[256];
    if (threadIdx.x < 128) {
        aws[threadIdx.x] = aw[(size_t)b * LL + threadIdx.x];
        aws[threadIdx.x + 128] = aw[(size_t)b * LL + 128 + threadIdx.x];
    }
    __syncthreads();
    float acc = 0.f;
    const float* e = enc + (size_t)b * HH + hc;
    for (int l0 = 0; l0 < LL; l0 += 16) {
        float v[16];
#pragma unroll
        for (int u = 0; u < 16; u++)
            v[u] = e[(size_t)(l0 + u) * BB * HH];
#pragma unroll
        for (int u = 0; u < 16; u++)
            acc += aws[l0 + u] * v[u];
    }
    cat[(size_t)b * 2048 + 1024 + hc] = acc;
}

// ================= launch =====================================================
extern "C" void kernel_launch(void* const* d_in, const int* in_sizes, int n_in,
                              void* d_out, int out_size) {
    const int*   seq  = (const int*)d_in[0];
    const float* h0   = (const float*)d_in[1];
    const float* enc  = (const float*)d_in[2];
    const float* emb  = (const float*)d_in[3];
    const float* w_ih = (const float*)d_in[4];
    const float* w_hh = (const float*)d_in[5];
    const float* b_ih = (const float*)d_in[6];
    const float* b_hh = (const float*)d_in[7];
    const float* attw = (const float*)d_in[8];
    const float* attb = (const float*)d_in[9];
    const float* cw   = (const float*)d_in[10];
    const float* cb   = (const float*)d_in[11];
    const float* ow   = (const float*)d_in[12];
    const float* ob   = (const float*)d_in[13];

    float* out        = (float*)d_out;                  // [B, V]
    float* out_hidden = out + (size_t)BB * VV;          // [B, H]
    float* out_attn   = out_hidden + (size_t)BB * HH;   // [B, L]

    __nv_bfloat16 *xhi, *xlo, *hhi, *hlo, *chi, *clo;
    float *gi, *gh, *cat, *hb, *q, *qp, *sc, *aw, *cp;
    cudaGetSymbolAddress((void**)&xhi, g_xhi);
    cudaGetSymbolAddress((void**)&xlo, g_xlo);
    cudaGetSymbolAddress((void**)&hhi, g_hhi);
    cudaGetSymbolAddress((void**)&hlo, g_hlo);
    cudaGetSymbolAddress((void**)&chi, g_chi);
    cudaGetSymbolAddress((void**)&clo, g_clo);
    cudaGetSymbolAddress((void**)&gi, g_gi);
    cudaGetSymbolAddress((void**)&gh, g_gh);
    cudaGetSymbolAddress((void**)&cat, g_cat);
    cudaGetSymbolAddress((void**)&hb, g_hb);
    cudaGetSymbolAddress((void**)&q, g_q);
    cudaGetSymbolAddress((void**)&qp, g_qpart);
    cudaGetSymbolAddress((void**)&sc, g_scores);
    cudaGetSymbolAddress((void**)&aw, g_aw);
    cudaGetSymbolAddress((void**)&cp, g_cpart);

    // 1) hi/lo splits: emb gather + h0, one launch
    split_all<<<128, 256>>>(seq, emb, h0, xhi, xlo, hhi, hlo);

    // 2) GRU gate GEMMs on tensor cores, split-K=2 (96 CTAs)
    hmma_gemm<<<dim3(24, 2, 2), 256>>>(xhi, xlo, w_ih, gi,
                                       hhi, hlo, w_hh, gh,
                                       nullptr, H3, EE, H3, (long)BB * H3);

    // 3) gates -> h_new (+hidden output, cat rows, hb reduction)
    gru_combine_hb<<<BB, 256>>>(gi, gh, b_ih, b_hh, h0, attb, cat, out_hidden, hb);

    // 4) q = h_new @ attn_w  (SIMT, split-K=16 + reduce)
    gemm_nn<<<dim3(8, 16), 128>>>(cat, 2048, attw, HH, qp, HH, HH);
    reduce_ba<<<(BB * HH) / 256, 256>>>(qp, 16, BB * HH, HH, nullptr, q, 0);

    // 5) scores = q . enc + hb ; softmax ; context
    scores_kernel<<<2048, 256>>>(q, enc, hb, sc);
    softmax_kernel<<<BB, 256>>>(sc, aw, out_attn);
    context_kernel<<<dim3(BB, 8), 128>>>(aw, enc, cat);

    // 6) concat_out = tanh([h_new|context] @ concat_w^T + concat_b), fused split
    gemm_tn<<<dim3(8, 16), 128>>>(cat, 2048, cw, 2048, cp, HH, 2048);
    reduce_tanh_split<<<(BB * HH) / 256, 256>>>(cp, cb, chi, clo);

    // 7) big V-GEMM on tensor cores
    hmma_gemm<<<dim3((VV + 127) / 128, 1, 1), 256>>>(
        chi, clo, ow, out, chi, clo, ow, out, ob, VV, HH, VV, 0);
}